// round 14
// baseline (speedup 1.0000x reference)
#include <cuda_runtime.h>

#define B_    8
#define N_    8192
#define M_    2048
#define C_    64
#define K_    32
#define CH_   67
#define ROWW  96      // 384B rows = 3 x 128B lines
#define CELLS_ 1000
#define HMAX  256

// Scratch (device globals — no allocation allowed)
__device__ float  g_ptsT[B_ * N_ * ROWW];
__device__ int    g_idx[B_ * M_ * K_];
__device__ int    g_cellstart[B_ * (CELLS_ + 1)];
__device__ float4 g_pts4[B_ * N_];               // cell-sorted (x,y,z,idx-bits)
__device__ int    g_mord[B_ * M_];               // cell-sorted center order

__device__ __forceinline__ int cell1d(float v) {
    int c = (int)(v * 10.0f);
    return c > 9 ? 9 : (c < 0 ? 0 : c);
}

// ---------------------------------------------------------------------------
// Kernel A: pack + transpose (B,3,N)+(B,64,N) -> ptsT[b][n][67 (pad 96)]
// ---------------------------------------------------------------------------
__global__ void __launch_bounds__(256) transpose_k(const float* __restrict__ pc,
                                                   const float* __restrict__ feat) {
    __shared__ float tile[CH_][33];
    int b  = blockIdx.y;
    int n0 = blockIdx.x * 32;
    int tx = threadIdx.x;
    int ty = threadIdx.y;

    for (int ch = ty; ch < CH_; ch += 8) {
        float v = (ch < 3)
            ? pc[((size_t)(b * 3 + ch)) * N_ + n0 + tx]
            : feat[((size_t)(b * C_ + (ch - 3))) * N_ + n0 + tx];
        tile[ch][tx] = v;
    }
    __syncthreads();

    for (int r = ty; r < 32; r += 8) {
        float* row = g_ptsT + (size_t)(b * N_ + n0 + r) * ROWW;
        row[tx]      = tile[tx][r];
        row[32 + tx] = tile[32 + tx][r];
        if (tx < 3) row[64 + tx] = tile[64 + tx][r];
    }
}

// ---------------------------------------------------------------------------
// Fused grid build: one CTA per batch.
//   points: count -> scan -> scatter (cell-sorted float4)
//   centers: count -> scan -> scatter (cell-sorted processing order g_mord)
// ---------------------------------------------------------------------------
#define PPT (N_ / 1024)   // 8
#define CPT (M_ / 1024)   // 2
__global__ void __launch_bounds__(1024) buildgrid_k(const float* __restrict__ pc,
                                                    const float* __restrict__ cc) {
    __shared__ int scnt[CELLS_];
    __shared__ int scur[CELLS_];
    __shared__ int wsum[32];

    int b = blockIdx.x;
    int t = threadIdx.x;
    int lane = t & 31;
    int wid = t >> 5;

    for (int i = t; i < CELLS_; i += 1024) scnt[i] = 0;
    __syncthreads();

    // ---- points ----
    const float* P = pc + (size_t)b * 3 * N_;
    float x[PPT], y[PPT], z[PPT];
    int cell[PPT];
    #pragma unroll
    for (int i = 0; i < PPT; i++) {
        int n = i * 1024 + t;
        x[i] = P[n]; y[i] = P[N_ + n]; z[i] = P[2 * N_ + n];
        cell[i] = (cell1d(x[i]) * 10 + cell1d(y[i])) * 10 + cell1d(z[i]);
        atomicAdd(&scnt[cell[i]], 1);
    }
    __syncthreads();

    {   // scan point counts
        int v = (t < CELLS_) ? scnt[t] : 0;
        int val = v;
        #pragma unroll
        for (int o = 1; o < 32; o <<= 1) {
            int u = __shfl_up_sync(0xffffffffu, v, o);
            if (lane >= o) v += u;
        }
        if (lane == 31) wsum[wid] = v;
        __syncthreads();
        if (wid == 0) {
            int w = wsum[lane];
            #pragma unroll
            for (int o = 1; o < 32; o <<= 1) {
                int u = __shfl_up_sync(0xffffffffu, w, o);
                if (lane >= o) w += u;
            }
            wsum[lane] = w;
        }
        __syncthreads();
        int incl = v + (wid > 0 ? wsum[wid - 1] : 0);
        int excl = incl - val;
        if (t < CELLS_) {
            g_cellstart[b * (CELLS_ + 1) + t] = excl;
            scur[t] = excl;
        }
        if (t == CELLS_ - 1) g_cellstart[b * (CELLS_ + 1) + CELLS_] = incl;
    }
    __syncthreads();

    size_t bo = (size_t)b * N_;
    #pragma unroll
    for (int i = 0; i < PPT; i++) {
        int n = i * 1024 + t;
        int pos = atomicAdd(&scur[cell[i]], 1);
        g_pts4[bo + pos] = make_float4(x[i], y[i], z[i], __int_as_float(n));
    }
    __syncthreads();

    // ---- centers: bin into cell-sorted processing order ----
    for (int i = t; i < CELLS_; i += 1024) scnt[i] = 0;
    __syncthreads();

    const float* CC = cc + (size_t)b * 3 * M_;
    int ccell[CPT];
    #pragma unroll
    for (int i = 0; i < CPT; i++) {
        int m = i * 1024 + t;
        float mx = CC[m], my = CC[M_ + m], mz = CC[2 * M_ + m];
        ccell[i] = (cell1d(mx) * 10 + cell1d(my)) * 10 + cell1d(mz);
        atomicAdd(&scnt[ccell[i]], 1);
    }
    __syncthreads();

    {   // scan center counts
        int v = (t < CELLS_) ? scnt[t] : 0;
        int val = v;
        #pragma unroll
        for (int o = 1; o < 32; o <<= 1) {
            int u = __shfl_up_sync(0xffffffffu, v, o);
            if (lane >= o) v += u;
        }
        if (lane == 31) wsum[wid] = v;
        __syncthreads();
        if (wid == 0) {
            int w = wsum[lane];
            #pragma unroll
            for (int o = 1; o < 32; o <<= 1) {
                int u = __shfl_up_sync(0xffffffffu, w, o);
                if (lane >= o) w += u;
            }
            wsum[lane] = w;
        }
        __syncthreads();
        int incl = v + (wid > 0 ? wsum[wid - 1] : 0);
        if (t < CELLS_) scur[t] = incl - val;
    }
    __syncthreads();

    #pragma unroll
    for (int i = 0; i < CPT; i++) {
        int m = i * 1024 + t;
        int pos = atomicAdd(&scur[ccell[i]], 1);
        g_mord[b * M_ + pos] = m;
    }
}

// ---------------------------------------------------------------------------
// Selection: 32 smallest indices from per-warp hit buffer (unordered).
// ---------------------------------------------------------------------------
template <int R>
__device__ __forceinline__ int select32(const int* __restrict__ hb, int cl,
                                        int cnt, int lane) {
    unsigned v[R];
    #pragma unroll
    for (int r = 0; r < R; r++) {
        int p = lane + 32 * r;
        v[r] = (p < cl) ? (unsigned)hb[p] : 0xffffffffu;
    }
    unsigned first = 0, kth = 0xffffffffu;
    #pragma unroll 1
    for (int it = 0; it < K_; it++) {
        unsigned lm = v[0];
        #pragma unroll
        for (int r = 1; r < R; r++) lm = min(lm, v[r]);
        unsigned mn = __reduce_min_sync(0xffffffffu, lm);
        if (mn == 0xffffffffu) break;
        if (it == 0) first = mn;
        if (it == lane) kth = mn;
        #pragma unroll
        for (int r = 0; r < R; r++) v[r] = (v[r] == mn) ? 0xffffffffu : v[r];
    }
    return (cnt == 0) ? 0 : ((lane < cnt) ? (int)kth : (int)first);
}

// ---------------------------------------------------------------------------
// Kernel B: grid ball query. One warp per center, centers processed in
// cell-sorted order (warps in a CTA share candidate ranges -> L1 reuse).
// Exact hit test replicates reference numerics.
// ---------------------------------------------------------------------------
#define WARPS_Q 8
__global__ void __launch_bounds__(32 * WARPS_Q)
query_k(const float* __restrict__ cc) {
    __shared__ int hits[WARPS_Q][HMAX];
    int b    = blockIdx.y;
    int warp = threadIdx.x >> 5;
    int lane = threadIdx.x & 31;
    unsigned lmask_lt = (1u << lane) - 1u;
    int m = g_mord[b * M_ + blockIdx.x * WARPS_Q + warp];
    int* hb = hits[warp];

    float cx = cc[(size_t)(b * 3 + 0) * M_ + m];
    float cy = cc[(size_t)(b * 3 + 1) * M_ + m];
    float cz = cc[(size_t)(b * 3 + 2) * M_ + m];
    float c2 = __fadd_rn(__fadd_rn(__fmul_rn(cx, cx), __fmul_rn(cy, cy)),
                         __fmul_rn(cz, cz));
    const float R2 = 0.01f;

    int icx = cell1d(cx), icy = cell1d(cy), icz = cell1d(cz);
    int zlo = icz > 0 ? icz - 1 : 0;
    int zhi = icz < 9 ? icz + 1 : 9;
    int xlo = icx > 0 ? icx - 1 : 0, xhi = icx < 9 ? icx + 1 : 9;
    int ylo = icy > 0 ? icy - 1 : 0, yhi = icy < 9 ? icy + 1 : 9;

    const int* cs = g_cellstart + b * (CELLS_ + 1);
    size_t bo = (size_t)b * N_;
    int cnt = 0;

    for (int dx = xlo; dx <= xhi; dx++) {
        for (int dy = ylo; dy <= yhi; dy++) {
            int base = (dx * 10 + dy) * 10;
            int s = cs[base + zlo];
            int e = cs[base + zhi + 1];
            for (int j0 = s; j0 < e; j0 += 32) {
                int j = j0 + lane;
                bool act = j < e;
                float4 p = g_pts4[bo + (act ? j : s)];
                float q = __fadd_rn(__fadd_rn(__fmul_rn(p.x, p.x), __fmul_rn(p.y, p.y)),
                                    __fmul_rn(p.z, p.z));
                float dot = __fmaf_rn(cz, p.z, __fmaf_rn(cy, p.y, __fmul_rn(cx, p.x)));
                float d2  = __fsub_rn(__fadd_rn(c2, q), __fadd_rn(dot, dot));
                bool hit = act && (d2 < R2);
                unsigned mask = __ballot_sync(0xffffffffu, hit);
                if (hit) {
                    int pos = cnt + __popc(mask & lmask_lt);
                    if (pos < HMAX) hb[pos] = __float_as_int(p.w);
                }
                cnt += __popc(mask);
            }
        }
    }
    __syncwarp();

    int cl = cnt > HMAX ? HMAX : cnt;
    int res;
    if (cl <= 32)       res = select32<1>(hb, cl, cnt, lane);
    else if (cl <= 64)  res = select32<2>(hb, cl, cnt, lane);
    else if (cl <= 128) res = select32<4>(hb, cl, cnt, lane);
    else                res = select32<8>(hb, cl, cnt, lane);

    g_idx[((size_t)b * M_ + m) * K_ + lane] = res;
}

// ---------------------------------------------------------------------------
// Kernel C: gather. One warp per center, centers in cell-sorted order so a
// CTA's 8 centers are spatially clustered -> neighbor rows hit L1.
// Two channel passes over a 35x33 tile; full-warp aligned LDG, conflict-free
// stride-33 STS, coalesced 128B STG.
// ---------------------------------------------------------------------------
#define WARPS_C 8
#define TILE_W 33
#define TILE_ROWS 35
__global__ void __launch_bounds__(32 * WARPS_C)
gather_k(const float* __restrict__ cc, float* __restrict__ out) {
    extern __shared__ float smc[];   // WARPS_C tiles of [35][33]
    int b    = blockIdx.y;
    int warp = threadIdx.x >> 5;
    int lane = threadIdx.x & 31;
    int m = g_mord[b * M_ + blockIdx.x * WARPS_C + warp];
    float* tile = smc + warp * (TILE_ROWS * TILE_W);

    int my_i = g_idx[((size_t)b * M_ + m) * K_ + lane];

    size_t obase = (((size_t)b * CH_) * M_ + m) * K_ + lane;
    const size_t cstride = (size_t)M_ * K_;
    const float* pbase = g_ptsT + (size_t)b * N_ * ROWW;

    // ---- Pass A: channels [0, 32) ----
    #pragma unroll 8
    for (int j = 0; j < K_; j++) {
        int ij = __shfl_sync(0xffffffffu, my_i, j);
        tile[lane * TILE_W + j] = pbase[(size_t)ij * ROWW + lane];
    }
    __syncwarp();

    float cx = cc[(size_t)(b * 3 + 0) * M_ + m];
    float cy = cc[(size_t)(b * 3 + 1) * M_ + m];
    float cz = cc[(size_t)(b * 3 + 2) * M_ + m];
    out[obase + 0 * cstride] = __fsub_rn(tile[0 * TILE_W + lane], cx);
    out[obase + 1 * cstride] = __fsub_rn(tile[1 * TILE_W + lane], cy);
    out[obase + 2 * cstride] = __fsub_rn(tile[2 * TILE_W + lane], cz);
    #pragma unroll
    for (int c = 3; c < 32; c++)
        out[obase + (size_t)c * cstride] = tile[c * TILE_W + lane];
    __syncwarp();

    // ---- Pass B: channels [32, 67) ----
    #pragma unroll 8
    for (int j = 0; j < K_; j++) {
        int ij = __shfl_sync(0xffffffffu, my_i, j);
        const float* row = pbase + (size_t)ij * ROWW;
        tile[lane * TILE_W + j] = row[32 + lane];
        if (lane < 3) tile[(32 + lane) * TILE_W + j] = row[64 + lane];
    }
    __syncwarp();

    #pragma unroll
    for (int c = 0; c < TILE_ROWS; c++)
        out[obase + (size_t)(32 + c) * cstride] = tile[c * TILE_W + lane];
}

// ---------------------------------------------------------------------------
extern "C" void kernel_launch(void* const* d_in, const int* in_sizes, int n_in,
                              void* d_out, int out_size) {
    const float* points_coords  = (const float*)d_in[0];   // (8, 3, 8192)
    const float* centers_coords = (const float*)d_in[1];   // (8, 3, 2048)
    const float* points_feats   = (const float*)d_in[2];   // (8, 64, 8192)
    float* out = (float*)d_out;                            // (8, 67, 2048, 32)

    const int smem_g = WARPS_C * TILE_ROWS * TILE_W * (int)sizeof(float);

    static bool init_done = false;
    static cudaStream_t s1;
    static cudaEvent_t e_fork, e_join;
    if (!init_done) {
        cudaFuncSetAttribute(gather_k, cudaFuncAttributeMaxDynamicSharedMemorySize, smem_g);
        cudaStreamCreateWithFlags(&s1, cudaStreamNonBlocking);
        cudaEventCreateWithFlags(&e_fork, cudaEventDisableTiming);
        cudaEventCreateWithFlags(&e_join, cudaEventDisableTiming);
        init_done = true;
    }

    cudaStream_t s0 = 0;

    // Fork: transpose on s1; grid build + query on s0 (independent)
    cudaEventRecord(e_fork, s0);
    cudaStreamWaitEvent(s1, e_fork, 0);

    {
        dim3 grid(N_ / 32, B_);
        dim3 block(32, 8);
        transpose_k<<<grid, block, 0, s1>>>(points_coords, points_feats);
    }

    buildgrid_k<<<B_, 1024, 0, s0>>>(points_coords, centers_coords);
    {
        dim3 grid(M_ / WARPS_Q, B_);
        query_k<<<grid, 32 * WARPS_Q, 0, s0>>>(centers_coords);
    }

    // Join: gather needs g_ptsT (s1) and g_idx (s0)
    cudaEventRecord(e_join, s1);
    cudaStreamWaitEvent(s0, e_join, 0);

    {
        dim3 grid(M_ / WARPS_C, B_);
        gather_k<<<grid, 32 * WARPS_C, smem_g, s0>>>(centers_coords, out);
    }
}

// round 15
// speedup vs baseline: 1.0850x; 1.0850x over previous
#include <cuda_runtime.h>

#define B_    8
#define N_    8192
#define M_    2048
#define C_    64
#define K_    32
#define CH_   67
#define ROWW  96      // 384B rows = 3 x 128B lines
#define CELLS_ 1000
#define HMAX  256

// Scratch (device globals — no allocation allowed)
__device__ float  g_ptsT[B_ * N_ * ROWW];
__device__ int    g_cellstart[B_ * (CELLS_ + 1)];
__device__ float4 g_pts4[B_ * N_];               // cell-sorted (x,y,z,idx-bits)
__device__ int    g_mord[B_ * M_];               // cell-sorted center order

__device__ __forceinline__ int cell1d(float v) {
    int c = (int)(v * 10.0f);
    return c > 9 ? 9 : (c < 0 ? 0 : c);
}

// ---------------------------------------------------------------------------
// Kernel A: pack + transpose (B,3,N)+(B,64,N) -> ptsT[b][n][67 (pad 96)]
// ---------------------------------------------------------------------------
__global__ void __launch_bounds__(256) transpose_k(const float* __restrict__ pc,
                                                   const float* __restrict__ feat) {
    __shared__ float tile[CH_][33];
    int b  = blockIdx.y;
    int n0 = blockIdx.x * 32;
    int tx = threadIdx.x;
    int ty = threadIdx.y;

    for (int ch = ty; ch < CH_; ch += 8) {
        float v = (ch < 3)
            ? pc[((size_t)(b * 3 + ch)) * N_ + n0 + tx]
            : feat[((size_t)(b * C_ + (ch - 3))) * N_ + n0 + tx];
        tile[ch][tx] = v;
    }
    __syncthreads();

    for (int r = ty; r < 32; r += 8) {
        float* row = g_ptsT + (size_t)(b * N_ + n0 + r) * ROWW;
        row[tx]      = tile[tx][r];
        row[32 + tx] = tile[32 + tx][r];
        if (tx < 3) row[64 + tx] = tile[64 + tx][r];
    }
}

// ---------------------------------------------------------------------------
// Fused grid build: one CTA per batch.
//   points: count -> scan -> scatter (cell-sorted float4)
//   centers: count -> scan -> scatter (cell-sorted processing order g_mord)
// ---------------------------------------------------------------------------
#define PPT (N_ / 1024)   // 8
#define CPT (M_ / 1024)   // 2
__global__ void __launch_bounds__(1024) buildgrid_k(const float* __restrict__ pc,
                                                    const float* __restrict__ cc) {
    __shared__ int scnt[CELLS_];
    __shared__ int scur[CELLS_];
    __shared__ int wsum[32];

    int b = blockIdx.x;
    int t = threadIdx.x;
    int lane = t & 31;
    int wid = t >> 5;

    for (int i = t; i < CELLS_; i += 1024) scnt[i] = 0;
    __syncthreads();

    // ---- points ----
    const float* P = pc + (size_t)b * 3 * N_;
    float x[PPT], y[PPT], z[PPT];
    int cell[PPT];
    #pragma unroll
    for (int i = 0; i < PPT; i++) {
        int n = i * 1024 + t;
        x[i] = P[n]; y[i] = P[N_ + n]; z[i] = P[2 * N_ + n];
        cell[i] = (cell1d(x[i]) * 10 + cell1d(y[i])) * 10 + cell1d(z[i]);
        atomicAdd(&scnt[cell[i]], 1);
    }
    __syncthreads();

    {   // scan point counts
        int v = (t < CELLS_) ? scnt[t] : 0;
        int val = v;
        #pragma unroll
        for (int o = 1; o < 32; o <<= 1) {
            int u = __shfl_up_sync(0xffffffffu, v, o);
            if (lane >= o) v += u;
        }
        if (lane == 31) wsum[wid] = v;
        __syncthreads();
        if (wid == 0) {
            int w = wsum[lane];
            #pragma unroll
            for (int o = 1; o < 32; o <<= 1) {
                int u = __shfl_up_sync(0xffffffffu, w, o);
                if (lane >= o) w += u;
            }
            wsum[lane] = w;
        }
        __syncthreads();
        int incl = v + (wid > 0 ? wsum[wid - 1] : 0);
        int excl = incl - val;
        if (t < CELLS_) {
            g_cellstart[b * (CELLS_ + 1) + t] = excl;
            scur[t] = excl;
        }
        if (t == CELLS_ - 1) g_cellstart[b * (CELLS_ + 1) + CELLS_] = incl;
    }
    __syncthreads();

    size_t bo = (size_t)b * N_;
    #pragma unroll
    for (int i = 0; i < PPT; i++) {
        int n = i * 1024 + t;
        int pos = atomicAdd(&scur[cell[i]], 1);
        g_pts4[bo + pos] = make_float4(x[i], y[i], z[i], __int_as_float(n));
    }
    __syncthreads();

    // ---- centers: bin into cell-sorted processing order ----
    for (int i = t; i < CELLS_; i += 1024) scnt[i] = 0;
    __syncthreads();

    const float* CC = cc + (size_t)b * 3 * M_;
    int ccell[CPT];
    #pragma unroll
    for (int i = 0; i < CPT; i++) {
        int m = i * 1024 + t;
        float mx = CC[m], my = CC[M_ + m], mz = CC[2 * M_ + m];
        ccell[i] = (cell1d(mx) * 10 + cell1d(my)) * 10 + cell1d(mz);
        atomicAdd(&scnt[ccell[i]], 1);
    }
    __syncthreads();

    {   // scan center counts
        int v = (t < CELLS_) ? scnt[t] : 0;
        int val = v;
        #pragma unroll
        for (int o = 1; o < 32; o <<= 1) {
            int u = __shfl_up_sync(0xffffffffu, v, o);
            if (lane >= o) v += u;
        }
        if (lane == 31) wsum[wid] = v;
        __syncthreads();
        if (wid == 0) {
            int w = wsum[lane];
            #pragma unroll
            for (int o = 1; o < 32; o <<= 1) {
                int u = __shfl_up_sync(0xffffffffu, w, o);
                if (lane >= o) w += u;
            }
            wsum[lane] = w;
        }
        __syncthreads();
        int incl = v + (wid > 0 ? wsum[wid - 1] : 0);
        if (t < CELLS_) scur[t] = incl - val;
    }
    __syncthreads();

    #pragma unroll
    for (int i = 0; i < CPT; i++) {
        int m = i * 1024 + t;
        int pos = atomicAdd(&scur[ccell[i]], 1);
        g_mord[b * M_ + pos] = m;
    }
}

// ---------------------------------------------------------------------------
// Selection: 32 smallest indices from per-warp hit buffer (unordered).
// ---------------------------------------------------------------------------
template <int R>
__device__ __forceinline__ int select32(const int* __restrict__ hb, int cl,
                                        int cnt, int lane) {
    unsigned v[R];
    #pragma unroll
    for (int r = 0; r < R; r++) {
        int p = lane + 32 * r;
        v[r] = (p < cl) ? (unsigned)hb[p] : 0xffffffffu;
    }
    unsigned first = 0, kth = 0xffffffffu;
    #pragma unroll 1
    for (int it = 0; it < K_; it++) {
        unsigned lm = v[0];
        #pragma unroll
        for (int r = 1; r < R; r++) lm = min(lm, v[r]);
        unsigned mn = __reduce_min_sync(0xffffffffu, lm);
        if (mn == 0xffffffffu) break;
        if (it == 0) first = mn;
        if (it == lane) kth = mn;
        #pragma unroll
        for (int r = 0; r < R; r++) v[r] = (v[r] == mn) ? 0xffffffffu : v[r];
    }
    return (cnt == 0) ? 0 : ((lane < cnt) ? (int)kth : (int)first);
}

// ---------------------------------------------------------------------------
// FUSED kernel: ball query + select + gather, one warp per center.
// Hit buffer aliases the first 1KB of the warp's gather tile (dead after
// select32 pulls it into registers). No g_idx round trip, no global barrier
// between query and gather.
// ---------------------------------------------------------------------------
#define WARPS_F 8
#define TILE_W 33
#define TILE_ROWS 35
__global__ void __launch_bounds__(32 * WARPS_F)
qg_fused_k(const float* __restrict__ cc, float* __restrict__ out) {
    extern __shared__ float smc[];   // WARPS_F tiles of [35][33]
    int b    = blockIdx.y;
    int warp = threadIdx.x >> 5;
    int lane = threadIdx.x & 31;
    unsigned lmask_lt = (1u << lane) - 1u;
    int m = g_mord[b * M_ + blockIdx.x * WARPS_F + warp];
    float* tile = smc + warp * (TILE_ROWS * TILE_W);
    int* hb = (int*)tile;            // aliases tile; dead before tile use

    // ---------------- query ----------------
    float cx = cc[(size_t)(b * 3 + 0) * M_ + m];
    float cy = cc[(size_t)(b * 3 + 1) * M_ + m];
    float cz = cc[(size_t)(b * 3 + 2) * M_ + m];
    float c2 = __fadd_rn(__fadd_rn(__fmul_rn(cx, cx), __fmul_rn(cy, cy)),
                         __fmul_rn(cz, cz));
    const float R2 = 0.01f;

    int icx = cell1d(cx), icy = cell1d(cy), icz = cell1d(cz);
    int zlo = icz > 0 ? icz - 1 : 0;
    int zhi = icz < 9 ? icz + 1 : 9;
    int xlo = icx > 0 ? icx - 1 : 0, xhi = icx < 9 ? icx + 1 : 9;
    int ylo = icy > 0 ? icy - 1 : 0, yhi = icy < 9 ? icy + 1 : 9;

    const int* cs = g_cellstart + b * (CELLS_ + 1);
    size_t bo = (size_t)b * N_;
    int cnt = 0;

    for (int dx = xlo; dx <= xhi; dx++) {
        for (int dy = ylo; dy <= yhi; dy++) {
            int base = (dx * 10 + dy) * 10;
            int s = cs[base + zlo];
            int e = cs[base + zhi + 1];
            for (int j0 = s; j0 < e; j0 += 32) {
                int j = j0 + lane;
                bool act = j < e;
                float4 p = g_pts4[bo + (act ? j : s)];
                float q = __fadd_rn(__fadd_rn(__fmul_rn(p.x, p.x), __fmul_rn(p.y, p.y)),
                                    __fmul_rn(p.z, p.z));
                float dot = __fmaf_rn(cz, p.z, __fmaf_rn(cy, p.y, __fmul_rn(cx, p.x)));
                float d2  = __fsub_rn(__fadd_rn(c2, q), __fadd_rn(dot, dot));
                bool hit = act && (d2 < R2);
                unsigned mask = __ballot_sync(0xffffffffu, hit);
                if (hit) {
                    int pos = cnt + __popc(mask & lmask_lt);
                    if (pos < HMAX) hb[pos] = __float_as_int(p.w);
                }
                cnt += __popc(mask);
            }
        }
    }
    __syncwarp();

    int cl = cnt > HMAX ? HMAX : cnt;
    int my_i;
    if (cl <= 32)       my_i = select32<1>(hb, cl, cnt, lane);
    else if (cl <= 64)  my_i = select32<2>(hb, cl, cnt, lane);
    else if (cl <= 128) my_i = select32<4>(hb, cl, cnt, lane);
    else                my_i = select32<8>(hb, cl, cnt, lane);
    __syncwarp();   // hb dead; tile may now be written

    // ---------------- gather ----------------
    size_t obase = (((size_t)b * CH_) * M_ + m) * K_ + lane;
    const size_t cstride = (size_t)M_ * K_;
    const float* pbase = g_ptsT + (size_t)b * N_ * ROWW;

    // Pass A: channels [0, 32)
    #pragma unroll 8
    for (int j = 0; j < K_; j++) {
        int ij = __shfl_sync(0xffffffffu, my_i, j);
        tile[lane * TILE_W + j] = pbase[(size_t)ij * ROWW + lane];
    }
    __syncwarp();

    out[obase + 0 * cstride] = __fsub_rn(tile[0 * TILE_W + lane], cx);
    out[obase + 1 * cstride] = __fsub_rn(tile[1 * TILE_W + lane], cy);
    out[obase + 2 * cstride] = __fsub_rn(tile[2 * TILE_W + lane], cz);
    #pragma unroll
    for (int c = 3; c < 32; c++)
        out[obase + (size_t)c * cstride] = tile[c * TILE_W + lane];
    __syncwarp();

    // Pass B: channels [32, 67)
    #pragma unroll 8
    for (int j = 0; j < K_; j++) {
        int ij = __shfl_sync(0xffffffffu, my_i, j);
        const float* row = pbase + (size_t)ij * ROWW;
        tile[lane * TILE_W + j] = row[32 + lane];
        if (lane < 3) tile[(32 + lane) * TILE_W + j] = row[64 + lane];
    }
    __syncwarp();

    #pragma unroll
    for (int c = 0; c < TILE_ROWS; c++)
        out[obase + (size_t)(32 + c) * cstride] = tile[c * TILE_W + lane];
}

// ---------------------------------------------------------------------------
extern "C" void kernel_launch(void* const* d_in, const int* in_sizes, int n_in,
                              void* d_out, int out_size) {
    const float* points_coords  = (const float*)d_in[0];   // (8, 3, 8192)
    const float* centers_coords = (const float*)d_in[1];   // (8, 3, 2048)
    const float* points_feats   = (const float*)d_in[2];   // (8, 64, 8192)
    float* out = (float*)d_out;                            // (8, 67, 2048, 32)

    const int smem_f = WARPS_F * TILE_ROWS * TILE_W * (int)sizeof(float);

    static bool init_done = false;
    static cudaStream_t s1;
    static cudaEvent_t e_fork, e_join;
    if (!init_done) {
        cudaFuncSetAttribute(qg_fused_k, cudaFuncAttributeMaxDynamicSharedMemorySize, smem_f);
        cudaStreamCreateWithFlags(&s1, cudaStreamNonBlocking);
        cudaEventCreateWithFlags(&e_fork, cudaEventDisableTiming);
        cudaEventCreateWithFlags(&e_join, cudaEventDisableTiming);
        init_done = true;
    }

    cudaStream_t s0 = 0;

    // Fork: transpose on s1; grid build on s0 (independent)
    cudaEventRecord(e_fork, s0);
    cudaStreamWaitEvent(s1, e_fork, 0);

    {
        dim3 grid(N_ / 32, B_);
        dim3 block(32, 8);
        transpose_k<<<grid, block, 0, s1>>>(points_coords, points_feats);
    }

    buildgrid_k<<<B_, 1024, 0, s0>>>(points_coords, centers_coords);

    // Join: fused kernel needs g_ptsT (s1) and grid (s0)
    cudaEventRecord(e_join, s1);
    cudaStreamWaitEvent(s0, e_join, 0);

    {
        dim3 grid(M_ / WARPS_F, B_);
        qg_fused_k<<<grid, 32 * WARPS_F, smem_f, s0>>>(centers_coords, out);
    }
}

// round 16
// speedup vs baseline: 1.2913x; 1.1902x over previous
#include <cuda_runtime.h>

#define B_    8
#define N_    8192
#define M_    2048
#define C_    64
#define K_    32
#define CH_   67
#define ROWW  96      // 384B rows = 3 x 128B lines
#define CELLS_ 1000
#define HMAX  256

// Scratch (device globals — no allocation allowed)
__device__ float  g_ptsT[B_ * N_ * ROWW];
__device__ int    g_cellstart[B_ * (CELLS_ + 1)];
__device__ float4 g_pts4[B_ * N_];               // cell-sorted (x,y,z,idx-bits)
__device__ int    g_mord[B_ * M_];               // cell-sorted center order

__device__ __forceinline__ int cell1d(float v) {
    int c = (int)(v * 10.0f);
    return c > 9 ? 9 : (c < 0 ? 0 : c);
}

// ---------------------------------------------------------------------------
// HYBRID kernel: blockIdx.x < 8  -> grid build for batch b
//                blockIdx.x >= 8 -> transpose one 128-point supertile
// 1024 threads; dynamic smem 35.4KB (transpose tile / build counters).
// ---------------------------------------------------------------------------
#define PPT (N_ / 1024)   // 8
#define CPT (M_ / 1024)   // 2
#define TS  132           // tile row stride (floats); 16B-aligned STS128
#define TILES_PER_B (N_ / 128)   // 64

__global__ void hybrid_build_transpose_k(const float* __restrict__ pc,
                                         const float* __restrict__ cc,
                                         const float* __restrict__ feat) {
    extern __shared__ float smraw[];
    int t = threadIdx.x;

    if (blockIdx.x >= B_) {
        // ===================== transpose path =====================
        float* tile = smraw;                 // [CH_][TS]
        int bid  = blockIdx.x - B_;          // 0..511
        int b    = bid >> 6;
        int n0   = (bid & 63) * 128;

        // Read: 67 channels x 32 float4 (=128 floats) = 2144 slots
        const float* pbc = pc + (size_t)b * 3 * N_;
        const float* fbc = feat + (size_t)b * C_ * N_;
        #pragma unroll
        for (int it = 0; it < 3; it++) {
            int idx = t + it * 1024;
            if (idx < CH_ * 32) {
                int ch = idx >> 5;
                int sg = idx & 31;
                const float* src = (ch < 3 ? pbc + (size_t)ch * N_
                                           : fbc + (size_t)(ch - 3) * N_) + n0 + sg * 4;
                float4 v = *(const float4*)src;
                *(float4*)(tile + ch * TS + sg * 4) = v;
            }
        }
        __syncthreads();

        // Write: warp per row, 4 rows per warp; 3 coalesced STG rounds per row
        int warp = t >> 5;
        int lane = t & 31;
        #pragma unroll
        for (int rr = 0; rr < 4; rr++) {
            int r = warp * 4 + rr;
            float* row = g_ptsT + (size_t)(b * N_ + n0 + r) * ROWW;
            row[lane]      = tile[lane * TS + r];
            row[32 + lane] = tile[(32 + lane) * TS + r];
            if (lane < 3) row[64 + lane] = tile[(64 + lane) * TS + r];
        }
        return;
    }

    // ===================== build path =====================
    int* scnt = (int*)smraw;
    int* scur = scnt + CELLS_;
    int* wsum = scur + CELLS_;

    int b = blockIdx.x;
    int lane = t & 31;
    int wid = t >> 5;

    for (int i = t; i < CELLS_; i += 1024) scnt[i] = 0;
    __syncthreads();

    // ---- points ----
    const float* P = pc + (size_t)b * 3 * N_;
    float x[PPT], y[PPT], z[PPT];
    int cell[PPT];
    #pragma unroll
    for (int i = 0; i < PPT; i++) {
        int n = i * 1024 + t;
        x[i] = P[n]; y[i] = P[N_ + n]; z[i] = P[2 * N_ + n];
        cell[i] = (cell1d(x[i]) * 10 + cell1d(y[i])) * 10 + cell1d(z[i]);
        atomicAdd(&scnt[cell[i]], 1);
    }
    __syncthreads();

    {   // scan point counts
        int v = (t < CELLS_) ? scnt[t] : 0;
        int val = v;
        #pragma unroll
        for (int o = 1; o < 32; o <<= 1) {
            int u = __shfl_up_sync(0xffffffffu, v, o);
            if (lane >= o) v += u;
        }
        if (lane == 31) wsum[wid] = v;
        __syncthreads();
        if (wid == 0) {
            int w = wsum[lane];
            #pragma unroll
            for (int o = 1; o < 32; o <<= 1) {
                int u = __shfl_up_sync(0xffffffffu, w, o);
                if (lane >= o) w += u;
            }
            wsum[lane] = w;
        }
        __syncthreads();
        int incl = v + (wid > 0 ? wsum[wid - 1] : 0);
        int excl = incl - val;
        if (t < CELLS_) {
            g_cellstart[b * (CELLS_ + 1) + t] = excl;
            scur[t] = excl;
        }
        if (t == CELLS_ - 1) g_cellstart[b * (CELLS_ + 1) + CELLS_] = incl;
    }
    __syncthreads();

    size_t bo = (size_t)b * N_;
    #pragma unroll
    for (int i = 0; i < PPT; i++) {
        int n = i * 1024 + t;
        int pos = atomicAdd(&scur[cell[i]], 1);
        g_pts4[bo + pos] = make_float4(x[i], y[i], z[i], __int_as_float(n));
    }
    __syncthreads();

    // ---- centers: bin into cell-sorted processing order ----
    for (int i = t; i < CELLS_; i += 1024) scnt[i] = 0;
    __syncthreads();

    const float* CC = cc + (size_t)b * 3 * M_;
    int ccell[CPT];
    #pragma unroll
    for (int i = 0; i < CPT; i++) {
        int m = i * 1024 + t;
        float mx = CC[m], my = CC[M_ + m], mz = CC[2 * M_ + m];
        ccell[i] = (cell1d(mx) * 10 + cell1d(my)) * 10 + cell1d(mz);
        atomicAdd(&scnt[ccell[i]], 1);
    }
    __syncthreads();

    {   // scan center counts
        int v = (t < CELLS_) ? scnt[t] : 0;
        int val = v;
        #pragma unroll
        for (int o = 1; o < 32; o <<= 1) {
            int u = __shfl_up_sync(0xffffffffu, v, o);
            if (lane >= o) v += u;
        }
        if (lane == 31) wsum[wid] = v;
        __syncthreads();
        if (wid == 0) {
            int w = wsum[lane];
            #pragma unroll
            for (int o = 1; o < 32; o <<= 1) {
                int u = __shfl_up_sync(0xffffffffu, w, o);
                if (lane >= o) w += u;
            }
            wsum[lane] = w;
        }
        __syncthreads();
        int incl = v + (wid > 0 ? wsum[wid - 1] : 0);
        if (t < CELLS_) scur[t] = incl - val;
    }
    __syncthreads();

    #pragma unroll
    for (int i = 0; i < CPT; i++) {
        int m = i * 1024 + t;
        int pos = atomicAdd(&scur[ccell[i]], 1);
        g_mord[b * M_ + pos] = m;
    }
}

// ---------------------------------------------------------------------------
// Selection: 32 smallest indices from per-warp hit buffer (unordered).
// ---------------------------------------------------------------------------
template <int R>
__device__ __forceinline__ int select32(const int* __restrict__ hb, int cl,
                                        int cnt, int lane) {
    unsigned v[R];
    #pragma unroll
    for (int r = 0; r < R; r++) {
        int p = lane + 32 * r;
        v[r] = (p < cl) ? (unsigned)hb[p] : 0xffffffffu;
    }
    unsigned first = 0, kth = 0xffffffffu;
    #pragma unroll 1
    for (int it = 0; it < K_; it++) {
        unsigned lm = v[0];
        #pragma unroll
        for (int r = 1; r < R; r++) lm = min(lm, v[r]);
        unsigned mn = __reduce_min_sync(0xffffffffu, lm);
        if (mn == 0xffffffffu) break;
        if (it == 0) first = mn;
        if (it == lane) kth = mn;
        #pragma unroll
        for (int r = 0; r < R; r++) v[r] = (v[r] == mn) ? 0xffffffffu : v[r];
    }
    return (cnt == 0) ? 0 : ((lane < cnt) ? (int)kth : (int)first);
}

// ---------------------------------------------------------------------------
// FUSED kernel: ball query + select + gather, one warp per center.
// Exact hit test replicates reference numerics; hit buffer aliases the
// warp's gather tile (dead after select32).
// ---------------------------------------------------------------------------
#define WARPS_F 8
#define TILE_W 33
#define TILE_ROWS 35
__global__ void __launch_bounds__(32 * WARPS_F)
qg_fused_k(const float* __restrict__ cc, float* __restrict__ out) {
    extern __shared__ float smc[];   // WARPS_F tiles of [35][33]
    int b    = blockIdx.y;
    int warp = threadIdx.x >> 5;
    int lane = threadIdx.x & 31;
    unsigned lmask_lt = (1u << lane) - 1u;
    int m = g_mord[b * M_ + blockIdx.x * WARPS_F + warp];
    float* tile = smc + warp * (TILE_ROWS * TILE_W);
    int* hb = (int*)tile;            // aliases tile; dead before tile use

    // ---------------- query ----------------
    float cx = cc[(size_t)(b * 3 + 0) * M_ + m];
    float cy = cc[(size_t)(b * 3 + 1) * M_ + m];
    float cz = cc[(size_t)(b * 3 + 2) * M_ + m];
    float c2 = __fadd_rn(__fadd_rn(__fmul_rn(cx, cx), __fmul_rn(cy, cy)),
                         __fmul_rn(cz, cz));
    const float R2 = 0.01f;

    int icx = cell1d(cx), icy = cell1d(cy), icz = cell1d(cz);
    int zlo = icz > 0 ? icz - 1 : 0;
    int zhi = icz < 9 ? icz + 1 : 9;
    int xlo = icx > 0 ? icx - 1 : 0, xhi = icx < 9 ? icx + 1 : 9;
    int ylo = icy > 0 ? icy - 1 : 0, yhi = icy < 9 ? icy + 1 : 9;

    const int* cs = g_cellstart + b * (CELLS_ + 1);
    size_t bo = (size_t)b * N_;
    int cnt = 0;

    for (int dx = xlo; dx <= xhi; dx++) {
        for (int dy = ylo; dy <= yhi; dy++) {
            int base = (dx * 10 + dy) * 10;
            int s = cs[base + zlo];
            int e = cs[base + zhi + 1];
            for (int j0 = s; j0 < e; j0 += 32) {
                int j = j0 + lane;
                bool act = j < e;
                float4 p = g_pts4[bo + (act ? j : s)];
                float q = __fadd_rn(__fadd_rn(__fmul_rn(p.x, p.x), __fmul_rn(p.y, p.y)),
                                    __fmul_rn(p.z, p.z));
                float dot = __fmaf_rn(cz, p.z, __fmaf_rn(cy, p.y, __fmul_rn(cx, p.x)));
                float d2  = __fsub_rn(__fadd_rn(c2, q), __fadd_rn(dot, dot));
                bool hit = act && (d2 < R2);
                unsigned mask = __ballot_sync(0xffffffffu, hit);
                if (hit) {
                    int pos = cnt + __popc(mask & lmask_lt);
                    if (pos < HMAX) hb[pos] = __float_as_int(p.w);
                }
                cnt += __popc(mask);
            }
        }
    }
    __syncwarp();

    int cl = cnt > HMAX ? HMAX : cnt;
    int my_i;
    if (cl <= 32)       my_i = select32<1>(hb, cl, cnt, lane);
    else if (cl <= 64)  my_i = select32<2>(hb, cl, cnt, lane);
    else if (cl <= 128) my_i = select32<4>(hb, cl, cnt, lane);
    else                my_i = select32<8>(hb, cl, cnt, lane);
    __syncwarp();   // hb dead; tile may now be written

    // ---------------- gather ----------------
    size_t obase = (((size_t)b * CH_) * M_ + m) * K_ + lane;
    const size_t cstride = (size_t)M_ * K_;
    const float* pbase = g_ptsT + (size_t)b * N_ * ROWW;

    // Pass A: channels [0, 32)
    #pragma unroll 8
    for (int j = 0; j < K_; j++) {
        int ij = __shfl_sync(0xffffffffu, my_i, j);
        tile[lane * TILE_W + j] = pbase[(size_t)ij * ROWW + lane];
    }
    __syncwarp();

    out[obase + 0 * cstride] = __fsub_rn(tile[0 * TILE_W + lane], cx);
    out[obase + 1 * cstride] = __fsub_rn(tile[1 * TILE_W + lane], cy);
    out[obase + 2 * cstride] = __fsub_rn(tile[2 * TILE_W + lane], cz);
    #pragma unroll
    for (int c = 3; c < 32; c++)
        out[obase + (size_t)c * cstride] = tile[c * TILE_W + lane];
    __syncwarp();

    // Pass B: channels [32, 67)
    #pragma unroll 8
    for (int j = 0; j < K_; j++) {
        int ij = __shfl_sync(0xffffffffu, my_i, j);
        const float* row = pbase + (size_t)ij * ROWW;
        tile[lane * TILE_W + j] = row[32 + lane];
        if (lane < 3) tile[(32 + lane) * TILE_W + j] = row[64 + lane];
    }
    __syncwarp();

    #pragma unroll
    for (int c = 0; c < TILE_ROWS; c++)
        out[obase + (size_t)(32 + c) * cstride] = tile[c * TILE_W + lane];
}

// ---------------------------------------------------------------------------
extern "C" void kernel_launch(void* const* d_in, const int* in_sizes, int n_in,
                              void* d_out, int out_size) {
    const float* points_coords  = (const float*)d_in[0];   // (8, 3, 8192)
    const float* centers_coords = (const float*)d_in[1];   // (8, 3, 2048)
    const float* points_feats   = (const float*)d_in[2];   // (8, 64, 8192)
    float* out = (float*)d_out;                            // (8, 67, 2048, 32)

    const int smem_h = CH_ * TS * (int)sizeof(float);                       // 35.4 KB
    const int smem_f = WARPS_F * TILE_ROWS * TILE_W * (int)sizeof(float);   // 37.0 KB

    // Single stream, two kernels, zero events.
    hybrid_build_transpose_k<<<B_ + B_ * TILES_PER_B, 1024, smem_h>>>(
        points_coords, centers_coords, points_feats);

    {
        dim3 grid(M_ / WARPS_F, B_);
        qg_fused_k<<<grid, 32 * WARPS_F, smem_f>>>(centers_coords, out);
    }
}

// round 17
// speedup vs baseline: 1.3455x; 1.0420x over previous
#include <cuda_runtime.h>

#define B_    8
#define N_    8192
#define M_    2048
#define C_    64
#define K_    32
#define CH_   67
#define ROWW  96      // 384B rows = 3 x 128B lines
#define CELLS_ 1000
#define HMAX  256
#define FULLM 0xffffffffu

// Scratch (device globals — no allocation allowed)
__device__ float  g_ptsT[B_ * N_ * ROWW];
__device__ int    g_cellstart[B_ * (CELLS_ + 1)];
__device__ float4 g_pts4[B_ * N_];               // cell-sorted (x,y,z,idx-bits)
__device__ int    g_mord[B_ * M_];               // cell-sorted center order

__device__ __forceinline__ int cell1d(float v) {
    int c = (int)(v * 10.0f);
    return c > 9 ? 9 : (c < 0 ? 0 : c);
}

// ---------------------------------------------------------------------------
// HYBRID kernel: blockIdx.x < 8  -> grid build for batch b
//                blockIdx.x >= 8 -> transpose one 128-point supertile
// ---------------------------------------------------------------------------
#define PPT (N_ / 1024)   // 8
#define CPT (M_ / 1024)   // 2
#define TS  132           // tile row stride (floats); 16B-aligned STS128
#define TILES_PER_B (N_ / 128)   // 64

__global__ void hybrid_build_transpose_k(const float* __restrict__ pc,
                                         const float* __restrict__ cc,
                                         const float* __restrict__ feat) {
    extern __shared__ float smraw[];
    int t = threadIdx.x;

    if (blockIdx.x >= B_) {
        // ===================== transpose path =====================
        float* tile = smraw;                 // [CH_][TS]
        int bid  = blockIdx.x - B_;          // 0..511
        int b    = bid >> 6;
        int n0   = (bid & 63) * 128;

        const float* pbc = pc + (size_t)b * 3 * N_;
        const float* fbc = feat + (size_t)b * C_ * N_;
        #pragma unroll
        for (int it = 0; it < 3; it++) {
            int idx = t + it * 1024;
            if (idx < CH_ * 32) {
                int ch = idx >> 5;
                int sg = idx & 31;
                const float* src = (ch < 3 ? pbc + (size_t)ch * N_
                                           : fbc + (size_t)(ch - 3) * N_) + n0 + sg * 4;
                float4 v = *(const float4*)src;
                *(float4*)(tile + ch * TS + sg * 4) = v;
            }
        }
        __syncthreads();

        int warp = t >> 5;
        int lane = t & 31;
        #pragma unroll
        for (int rr = 0; rr < 4; rr++) {
            int r = warp * 4 + rr;
            float* row = g_ptsT + (size_t)(b * N_ + n0 + r) * ROWW;
            row[lane]      = tile[lane * TS + r];
            row[32 + lane] = tile[(32 + lane) * TS + r];
            if (lane < 3) row[64 + lane] = tile[(64 + lane) * TS + r];
        }
        return;
    }

    // ===================== build path =====================
    int* scnt = (int*)smraw;
    int* scur = scnt + CELLS_;
    int* wsum = scur + CELLS_;

    int b = blockIdx.x;
    int lane = t & 31;
    int wid = t >> 5;

    for (int i = t; i < CELLS_; i += 1024) scnt[i] = 0;
    __syncthreads();

    const float* P = pc + (size_t)b * 3 * N_;
    float x[PPT], y[PPT], z[PPT];
    int cell[PPT];
    #pragma unroll
    for (int i = 0; i < PPT; i++) {
        int n = i * 1024 + t;
        x[i] = P[n]; y[i] = P[N_ + n]; z[i] = P[2 * N_ + n];
        cell[i] = (cell1d(x[i]) * 10 + cell1d(y[i])) * 10 + cell1d(z[i]);
        atomicAdd(&scnt[cell[i]], 1);
    }
    __syncthreads();

    {   // scan point counts
        int v = (t < CELLS_) ? scnt[t] : 0;
        int val = v;
        #pragma unroll
        for (int o = 1; o < 32; o <<= 1) {
            int u = __shfl_up_sync(FULLM, v, o);
            if (lane >= o) v += u;
        }
        if (lane == 31) wsum[wid] = v;
        __syncthreads();
        if (wid == 0) {
            int w = wsum[lane];
            #pragma unroll
            for (int o = 1; o < 32; o <<= 1) {
                int u = __shfl_up_sync(FULLM, w, o);
                if (lane >= o) w += u;
            }
            wsum[lane] = w;
        }
        __syncthreads();
        int incl = v + (wid > 0 ? wsum[wid - 1] : 0);
        int excl = incl - val;
        if (t < CELLS_) {
            g_cellstart[b * (CELLS_ + 1) + t] = excl;
            scur[t] = excl;
        }
        if (t == CELLS_ - 1) g_cellstart[b * (CELLS_ + 1) + CELLS_] = incl;
    }
    __syncthreads();

    size_t bo = (size_t)b * N_;
    #pragma unroll
    for (int i = 0; i < PPT; i++) {
        int n = i * 1024 + t;
        int pos = atomicAdd(&scur[cell[i]], 1);
        g_pts4[bo + pos] = make_float4(x[i], y[i], z[i], __int_as_float(n));
    }
    __syncthreads();

    // ---- centers ----
    for (int i = t; i < CELLS_; i += 1024) scnt[i] = 0;
    __syncthreads();

    const float* CC = cc + (size_t)b * 3 * M_;
    int ccell[CPT];
    #pragma unroll
    for (int i = 0; i < CPT; i++) {
        int m = i * 1024 + t;
        float mx = CC[m], my = CC[M_ + m], mz = CC[2 * M_ + m];
        ccell[i] = (cell1d(mx) * 10 + cell1d(my)) * 10 + cell1d(mz);
        atomicAdd(&scnt[ccell[i]], 1);
    }
    __syncthreads();

    {   // scan center counts
        int v = (t < CELLS_) ? scnt[t] : 0;
        int val = v;
        #pragma unroll
        for (int o = 1; o < 32; o <<= 1) {
            int u = __shfl_up_sync(FULLM, v, o);
            if (lane >= o) v += u;
        }
        if (lane == 31) wsum[wid] = v;
        __syncthreads();
        if (wid == 0) {
            int w = wsum[lane];
            #pragma unroll
            for (int o = 1; o < 32; o <<= 1) {
                int u = __shfl_up_sync(FULLM, w, o);
                if (lane >= o) w += u;
            }
            wsum[lane] = w;
        }
        __syncthreads();
        int incl = v + (wid > 0 ? wsum[wid - 1] : 0);
        if (t < CELLS_) scur[t] = incl - val;
    }
    __syncthreads();

    #pragma unroll
    for (int i = 0; i < CPT; i++) {
        int m = i * 1024 + t;
        int pos = atomicAdd(&scur[ccell[i]], 1);
        g_mord[b * M_ + pos] = m;
    }
}

// ---------------------------------------------------------------------------
// Warp bitonic sort (ascending), one value per lane.
// ---------------------------------------------------------------------------
__device__ __forceinline__ unsigned bitonic_sort32(unsigned v, int lane) {
    #pragma unroll
    for (int k = 2; k <= 32; k <<= 1) {
        #pragma unroll
        for (int j = k >> 1; j > 0; j >>= 1) {
            unsigned o = __shfl_xor_sync(FULLM, v, j);
            bool up = ((lane & k) == 0);
            bool lower = ((lane & j) == 0);
            unsigned mn = min(v, o), mx = max(v, o);
            v = (up == lower) ? mn : mx;
        }
    }
    return v;
}
// Cleanup of a bitonic sequence (ascending), 5 stages.
__device__ __forceinline__ unsigned bitonic_merge32(unsigned v, int lane) {
    #pragma unroll
    for (int j = 16; j > 0; j >>= 1) {
        unsigned o = __shfl_xor_sync(FULLM, v, j);
        unsigned mn = min(v, o), mx = max(v, o);
        v = ((lane & j) == 0) ? mn : mx;
    }
    return v;
}

// Fallback for rare cnt>64: serial min-extraction.
template <int R>
__device__ __forceinline__ int select32_slow(const int* __restrict__ hb, int cl,
                                             int cnt, int lane) {
    unsigned v[R];
    #pragma unroll
    for (int r = 0; r < R; r++) {
        int p = lane + 32 * r;
        v[r] = (p < cl) ? (unsigned)hb[p] : FULLM;
    }
    unsigned first = 0, kth = FULLM;
    #pragma unroll 1
    for (int it = 0; it < K_; it++) {
        unsigned lm = v[0];
        #pragma unroll
        for (int r = 1; r < R; r++) lm = min(lm, v[r]);
        unsigned mn = __reduce_min_sync(FULLM, lm);
        if (mn == FULLM) break;
        if (it == 0) first = mn;
        if (it == lane) kth = mn;
        #pragma unroll
        for (int r = 0; r < R; r++) v[r] = (v[r] == mn) ? FULLM : v[r];
    }
    return (cnt == 0) ? 0 : ((lane < cnt) ? (int)kth : (int)first);
}

// ---------------------------------------------------------------------------
// FUSED kernel: ball query + bitonic select + gather, one warp per center.
// ---------------------------------------------------------------------------
#define WARPS_F 8
#define TILE_W 33
#define TILE_ROWS 35
__global__ void __launch_bounds__(32 * WARPS_F)
qg_fused_k(const float* __restrict__ cc, float* __restrict__ out) {
    extern __shared__ float smc[];   // WARPS_F tiles of [35][33]
    int b    = blockIdx.y;
    int warp = threadIdx.x >> 5;
    int lane = threadIdx.x & 31;
    unsigned lmask_lt = (1u << lane) - 1u;
    int m = g_mord[b * M_ + blockIdx.x * WARPS_F + warp];
    float* tile = smc + warp * (TILE_ROWS * TILE_W);
    int* hb = (int*)tile;            // aliases tile; dead before tile use

    // ---------------- query ----------------
    float cx = cc[(size_t)(b * 3 + 0) * M_ + m];
    float cy = cc[(size_t)(b * 3 + 1) * M_ + m];
    float cz = cc[(size_t)(b * 3 + 2) * M_ + m];
    float c2 = __fadd_rn(__fadd_rn(__fmul_rn(cx, cx), __fmul_rn(cy, cy)),
                         __fmul_rn(cz, cz));
    const float R2 = 0.01f;

    int icx = cell1d(cx), icy = cell1d(cy), icz = cell1d(cz);
    int zlo = icz > 0 ? icz - 1 : 0;
    int zhi = icz < 9 ? icz + 1 : 9;
    int xlo = icx > 0 ? icx - 1 : 0, xhi = icx < 9 ? icx + 1 : 9;
    int ylo = icy > 0 ? icy - 1 : 0, yhi = icy < 9 ? icy + 1 : 9;

    const int* cs = g_cellstart + b * (CELLS_ + 1);
    size_t bo = (size_t)b * N_;
    int cnt = 0;

    for (int dx = xlo; dx <= xhi; dx++) {
        for (int dy = ylo; dy <= yhi; dy++) {
            int base = (dx * 10 + dy) * 10;
            int s = cs[base + zlo];
            int e = cs[base + zhi + 1];
            for (int j0 = s; j0 < e; j0 += 32) {
                int j = j0 + lane;
                bool act = j < e;
                float4 p = g_pts4[bo + (act ? j : s)];
                float q = __fadd_rn(__fadd_rn(__fmul_rn(p.x, p.x), __fmul_rn(p.y, p.y)),
                                    __fmul_rn(p.z, p.z));
                float dot = __fmaf_rn(cz, p.z, __fmaf_rn(cy, p.y, __fmul_rn(cx, p.x)));
                float d2  = __fsub_rn(__fadd_rn(c2, q), __fadd_rn(dot, dot));
                bool hit = act && (d2 < R2);
                unsigned mask = __ballot_sync(FULLM, hit);
                if (hit) {
                    int pos = cnt + __popc(mask & lmask_lt);
                    if (pos < HMAX) hb[pos] = __float_as_int(p.w);
                }
                cnt += __popc(mask);
            }
        }
    }
    __syncwarp();

    // ---------------- selection (32 smallest, ascending) ----------------
    int cl = cnt > HMAX ? HMAX : cnt;
    int my_i;
    if (cl <= 32) {
        unsigned v = (lane < cl) ? (unsigned)hb[lane] : FULLM;
        v = bitonic_sort32(v, lane);                 // lane == rank
        unsigned first = __shfl_sync(FULLM, v, 0);
        my_i = (cnt == 0) ? 0 : ((lane < cnt) ? (int)v : (int)first);
    } else if (cl <= 64) {
        unsigned v0 = (unsigned)hb[lane];
        unsigned v1 = (32 + lane < cl) ? (unsigned)hb[32 + lane] : FULLM;
        v0 = bitonic_sort32(v0, lane);
        v1 = bitonic_sort32(v1, lane);
        unsigned rev = __shfl_sync(FULLM, v1, 31 - lane);
        unsigned lo = min(v0, rev);                  // bitonic, holds 32 smallest
        lo = bitonic_merge32(lo, lane);              // sorted ascending
        unsigned first = __shfl_sync(FULLM, lo, 0);
        my_i = (lane < cnt) ? (int)lo : (int)first;  // cnt > 32 here
    } else if (cl <= 128) {
        my_i = select32_slow<4>(hb, cl, cnt, lane);
    } else {
        my_i = select32_slow<8>(hb, cl, cnt, lane);
    }
    __syncwarp();   // hb dead; tile may now be written

    // ---------------- gather ----------------
    size_t obase = (((size_t)b * CH_) * M_ + m) * K_ + lane;
    const size_t cstride = (size_t)M_ * K_;
    const float* pbase = g_ptsT + (size_t)b * N_ * ROWW;

    // Pass A: channels [0, 32)
    #pragma unroll 8
    for (int j = 0; j < K_; j++) {
        int ij = __shfl_sync(FULLM, my_i, j);
        tile[lane * TILE_W + j] = pbase[(size_t)ij * ROWW + lane];
    }
    __syncwarp();

    out[obase + 0 * cstride] = __fsub_rn(tile[0 * TILE_W + lane], cx);
    out[obase + 1 * cstride] = __fsub_rn(tile[1 * TILE_W + lane], cy);
    out[obase + 2 * cstride] = __fsub_rn(tile[2 * TILE_W + lane], cz);
    #pragma unroll
    for (int c = 3; c < 32; c++)
        out[obase + (size_t)c * cstride] = tile[c * TILE_W + lane];
    __syncwarp();

    // Pass B: channels [32, 67)
    #pragma unroll 8
    for (int j = 0; j < K_; j++) {
        int ij = __shfl_sync(FULLM, my_i, j);
        const float* row = pbase + (size_t)ij * ROWW;
        tile[lane * TILE_W + j] = row[32 + lane];
        if (lane < 3) tile[(32 + lane) * TILE_W + j] = row[64 + lane];
    }
    __syncwarp();

    #pragma unroll
    for (int c = 0; c < TILE_ROWS; c++)
        out[obase + (size_t)(32 + c) * cstride] = tile[c * TILE_W + lane];
}

// ---------------------------------------------------------------------------
extern "C" void kernel_launch(void* const* d_in, const int* in_sizes, int n_in,
                              void* d_out, int out_size) {
    const float* points_coords  = (const float*)d_in[0];   // (8, 3, 8192)
    const float* centers_coords = (const float*)d_in[1];   // (8, 3, 2048)
    const float* points_feats   = (const float*)d_in[2];   // (8, 64, 8192)
    float* out = (float*)d_out;                            // (8, 67, 2048, 32)

    const int smem_h = CH_ * TS * (int)sizeof(float);                       // 35.4 KB
    const int smem_f = WARPS_F * TILE_ROWS * TILE_W * (int)sizeof(float);   // 37.0 KB

    hybrid_build_transpose_k<<<B_ + B_ * TILES_PER_B, 1024, smem_h>>>(
        points_coords, centers_coords, points_feats);

    {
        dim3 grid(M_ / WARPS_F, B_);
        qg_fused_k<<<grid, 32 * WARPS_F, smem_f>>>(centers_coords, out);
    }
}